// round 15
// baseline (speedup 1.0000x reference)
#include <cuda_runtime.h>
#include <cuda_fp16.h>
#include <cstdint>

#define NEG_SLOPE 0.2f
#define GAT_EPS 1e-16f

static constexpr int Nn  = 50000;
static constexpr int Cc  = 64;
static constexpr int Hh  = 12;
static constexpr int Ee  = 400000;
static constexpr int Etot_c = Ee + Nn;
static constexpr int NC  = Hh * Cc;   // 768

// fused GEMM+scatter tiling: 64 src rows per block
static constexpr int GR = 64;
static constexpr int GP = 128;         // W panel cols
static constexpr int XS_PITCH = 68;    // 64 + 4
static constexpr int WS_PITCH = 132;   // 128 + 4
static constexpr int H_PITCH  = 776;   // 768 + 8 halfs -> row stride 1552B, bank-staggered
static constexpr int FUSED_SMEM =
    GR * XS_PITCH * 4 + Cc * WS_PITCH * 4 + GR * H_PITCH * 2;  // 150528 B

// ---- zeroed-every-launch blob: y | denom | cursor | done ----
static constexpr size_t ZB_DEN  = (size_t)Nn * Cc;
static constexpr size_t ZB_CUR  = ZB_DEN + (size_t)Nn * Hh;
static constexpr size_t ZB_DONE = ZB_CUR + Nn;
static constexpr size_t ZB_SIZE = ZB_DONE + 4;
__device__ float g_zbuf[ZB_SIZE];
#define G_Y    (g_zbuf)
#define G_DEN  (g_zbuf + ZB_DEN)
#define G_CUR  ((int*)(g_zbuf + ZB_CUR))
#define G_DONE ((int*)(g_zbuf + ZB_DONE))

// ---- other scratch ----
__device__ float    g_asrc[Nn * Hh];
__device__ float    g_dst2[Nn * 24];          // [0..11]=a_dst, [12..23]=inv denom/12
__device__ float    g_wa[Cc * 24];
__device__ int      g_bsum[256];
__device__ int2     g_srec[Etot_c];           // src-sorted (src,dst) pairs

__device__ __forceinline__ float lrelu(float v) {
    return v > 0.0f ? v : NEG_SLOPE * v;
}
__device__ __forceinline__ float to_tf32(float v) {
    uint32_t b;
    asm("cvt.rna.tf32.f32 %0, %1;" : "=r"(b) : "f"(v));
    return __uint_as_float(b);
}

// ---- K1: fold attention vectors through W ----
__global__ void k_wa(const float* __restrict__ W,
                     const float* __restrict__ att_src,
                     const float* __restrict__ att_dst) {
    int t = blockIdx.x * blockDim.x + threadIdx.x;
    if (t >= Cc * 24) return;
    int k = t / 24, j = t % 24;
    int h = j >> 1;
    const float* att = (j & 1) ? att_dst : att_src;
    float s = 0.0f;
    #pragma unroll 8
    for (int c = 0; c < Cc; c++) s += W[k * NC + h * Cc + c] * att[h * Cc + c];
    g_wa[k * 24 + j] = s;
}

// ---- K2: a_src/a_dst = x @ Wa  (128 rows, 512 threads) ----
__global__ void __launch_bounds__(512) k_attn(const float* __restrict__ x, int N) {
    __shared__ float xsh[128 * 65];
    __shared__ float was[64 * 24];
    int t = threadIdx.x;
    for (int i = t; i < 64 * 24; i += 512) was[i] = g_wa[i];
    int r0 = blockIdx.x * 128;
    for (int i = t; i < 2048; i += 512) {
        int rr = i >> 4, kk = (i & 15) << 2;
        float4 v = make_float4(0.f, 0.f, 0.f, 0.f);
        if (r0 + rr < N) v = ((const float4*)(x + (size_t)r0 * 64))[i];
        xsh[rr * 65 + kk + 0] = v.x;
        xsh[rr * 65 + kk + 1] = v.y;
        xsh[rr * 65 + kk + 2] = v.z;
        xsh[rr * 65 + kk + 3] = v.w;
    }
    __syncthreads();
    int r = t >> 2, q = t & 3;
    int n = r0 + r;
    float acc[6] = {0.f, 0.f, 0.f, 0.f, 0.f, 0.f};
    #pragma unroll 8
    for (int k = 0; k < 64; k++) {
        float xv = xsh[r * 65 + k];
        #pragma unroll
        for (int j = 0; j < 6; j++) acc[j] += xv * was[k * 24 + q * 6 + j];
    }
    if (n < N) {
        #pragma unroll
        for (int j = 0; j < 6; j++) {
            int jj = q * 6 + j, h = jj >> 1;
            if (jj & 1) g_dst2[n * 24 + h] = acc[j];
            else        g_asrc[n * 12 + h] = acc[j];
        }
    }
}

// ---- K3: fused edge pass: src-histogram + denom via vectorized REDs ----
__global__ void k_edge(const int* __restrict__ ei, int E, int N) {
    int e = blockIdx.x * blockDim.x + threadIdx.x;
    int Et = E + N;
    if (e >= Et) return;
    int s, d;
    if (e < E) { s = ei[e]; d = ei[E + e]; } else { s = d = e - E; }
    atomicAdd(&G_CUR[s], 1);
    const float4* As = (const float4*)(g_asrc + (size_t)s * 12);
    const float4* Ad = (const float4*)(g_dst2 + (size_t)d * 24);
    float* den = G_DEN + (size_t)d * 12;
    #pragma unroll
    for (int i = 0; i < 3; i++) {
        float4 a = As[i], b = Ad[i];
        float e0 = __expf(lrelu(a.x + b.x));
        float e1 = __expf(lrelu(a.y + b.y));
        float e2 = __expf(lrelu(a.z + b.z));
        float e3 = __expf(lrelu(a.w + b.w));
        asm volatile("red.global.add.v4.f32 [%0], {%1, %2, %3, %4};"
                     :: "l"(den + i * 4), "f"(e0), "f"(e1), "f"(e2), "f"(e3)
                     : "memory");
    }
}

// ---- K4: fused: invd + cursor scan + (last block) bsum scan ----
__global__ void k_scan1(int N, int nb) {
    __shared__ int wsum[8];
    __shared__ int isLast;
    int b = blockIdx.x, t = threadIdx.x, i = b * 256 + t;
    int lane = t & 31, w = t >> 5;

    if (i < N) {
        const float4* dn = (const float4*)(G_DEN + (size_t)i * 12);
        float4* q = (float4*)(g_dst2 + (size_t)i * 24 + 12);
        #pragma unroll
        for (int k = 0; k < 3; k++) {
            float4 v = dn[k], o;
            o.x = 1.0f / (v.x + GAT_EPS) * (1.0f / 12.0f);
            o.y = 1.0f / (v.y + GAT_EPS) * (1.0f / 12.0f);
            o.z = 1.0f / (v.z + GAT_EPS) * (1.0f / 12.0f);
            o.w = 1.0f / (v.w + GAT_EPS) * (1.0f / 12.0f);
            q[k] = o;
        }
    }

    int v = (i < N) ? G_CUR[i] : 0;
    int incl = v;
    #pragma unroll
    for (int o = 1; o < 32; o <<= 1) {
        int nv = __shfl_up_sync(~0u, incl, o);
        if (lane >= o) incl += nv;
    }
    if (lane == 31) wsum[w] = incl;
    __syncthreads();
    if (w == 0) {
        int s = (lane < 8) ? wsum[lane] : 0;
        #pragma unroll
        for (int o = 1; o < 8; o <<= 1) {
            int nv = __shfl_up_sync(~0u, s, o);
            if (lane >= o) s += nv;
        }
        if (lane < 8) wsum[lane] = s;
    }
    __syncthreads();
    int excl = (w > 0 ? wsum[w - 1] : 0) + incl - v;
    if (i < N) G_CUR[i] = excl;
    if (t == 255) g_bsum[b] = wsum[7];

    __threadfence();
    if (t == 0) {
        int prev = atomicAdd(G_DONE, 1);
        isLast = (prev == nb - 1) ? 1 : 0;
    }
    __syncthreads();
    if (isLast) {
        int val = (t < nb) ? g_bsum[t] : 0;
        int inc2 = val;
        #pragma unroll
        for (int o = 1; o < 32; o <<= 1) {
            int nv = __shfl_up_sync(~0u, inc2, o);
            if (lane >= o) inc2 += nv;
        }
        __syncthreads();
        if (lane == 31) wsum[w] = inc2;
        __syncthreads();
        if (w == 0) {
            int s = (lane < 8) ? wsum[lane] : 0;
            #pragma unroll
            for (int o = 1; o < 8; o <<= 1) {
                int nv = __shfl_up_sync(~0u, s, o);
                if (lane >= o) s += nv;
            }
            if (lane < 8) wsum[lane] = s;
        }
        __syncthreads();
        int ex2 = (w > 0 ? wsum[w - 1] : 0) + inc2 - val;
        if (t < nb) g_bsum[t] = ex2;
    }
}

// ---- K5: permute with fused block-offset add ----
__global__ void k_perm(const int* __restrict__ ei, int E, int N) {
    int e = blockIdx.x * blockDim.x + threadIdx.x;
    int Et = E + N;
    if (e >= Et) return;
    int s, d;
    if (e < E) { s = ei[e]; d = ei[E + e]; } else { s = d = e - E; }
    int pos = atomicAdd(&G_CUR[s], 1) + g_bsum[s >> 8];
    g_srec[pos] = make_int2(s, d);
}

// ---- K6: FUSED gemm + scatter. Block b: srcs [64b, 64b+64).
// Phase 1: h rows via tf32 mma -> fp16 smem tile (never touches DRAM).
// Phase 2: process this block's contiguous src-sorted edge range from smem.
__global__ void __launch_bounds__(256) k_gemm_scatter(const float* __restrict__ x,
                                                      const float* __restrict__ W,
                                                      int N, int Et) {
    extern __shared__ char smraw[];
    float* xs = (float*)smraw;                    // [64][68]
    float* ws = xs + GR * XS_PITCH;               // [64][132]
    __half* hs = (__half*)(ws + Cc * WS_PITCH);   // [64][776]

    int t = threadIdx.x;
    int lane = t & 31, w = t >> 5;
    int g4 = lane >> 2, t4 = lane & 3;
    int rg = w & 3, ch = w >> 2;                  // row group (16 rows), col half (64 cols)
    int r0 = blockIdx.x * GR;

    // ---- phase 1: x tile ----
    {
        const float4* x4 = (const float4*)(x + (size_t)r0 * Cc);
        #pragma unroll
        for (int j = 0; j < 4; j++) {
            int idx = t + j * 256;                // 1024 float4 = 64 rows x 16
            int row = idx >> 4, c4 = (idx & 15) << 2;
            float4 v = make_float4(0.f, 0.f, 0.f, 0.f);
            if (r0 + row < N) v = x4[idx];
            float* p = xs + row * XS_PITCH + c4;
            p[0] = to_tf32(v.x); p[1] = to_tf32(v.y);
            p[2] = to_tf32(v.z); p[3] = to_tf32(v.w);
        }
    }
    __syncthreads();

    uint32_t a[8][4];
    #pragma unroll
    for (int kk = 0; kk < 8; kk++) {
        int c0 = kk * 8 + t4;
        a[kk][0] = __float_as_uint(xs[(rg * 16 + g4)     * XS_PITCH + c0]);
        a[kk][1] = __float_as_uint(xs[(rg * 16 + g4 + 8) * XS_PITCH + c0]);
        a[kk][2] = __float_as_uint(xs[(rg * 16 + g4)     * XS_PITCH + c0 + 4]);
        a[kk][3] = __float_as_uint(xs[(rg * 16 + g4 + 8) * XS_PITCH + c0 + 4]);
    }

    for (int p = 0; p < NC / GP; p++) {
        __syncthreads();
        {   // W panel [64 k][128 cols]
            const float4* W4 = (const float4*)W;
            int n0f4 = p * (GP / 4);
            #pragma unroll
            for (int j = 0; j < 8; j++) {
                int idx = t + j * 256;
                int k = idx >> 5, n4 = (idx & 31) << 2;
                float4 v = W4[(size_t)k * (NC / 4) + n0f4 + (n4 >> 2)];
                float* q = ws + k * WS_PITCH + n4;
                q[0] = to_tf32(v.x); q[1] = to_tf32(v.y);
                q[2] = to_tf32(v.z); q[3] = to_tf32(v.w);
            }
        }
        __syncthreads();

        float c[8][4];
        #pragma unroll
        for (int nt = 0; nt < 8; nt++)
            #pragma unroll
            for (int q = 0; q < 4; q++) c[nt][q] = 0.0f;

        #pragma unroll
        for (int kk = 0; kk < 8; kk++) {
            const float* wrow0 = ws + (kk * 8 + t4) * WS_PITCH + ch * 64;
            const float* wrow1 = wrow0 + 4 * WS_PITCH;
            #pragma unroll
            for (int nt = 0; nt < 8; nt++) {
                uint32_t b0 = __float_as_uint(wrow0[nt * 8 + g4]);
                uint32_t b1 = __float_as_uint(wrow1[nt * 8 + g4]);
                asm volatile(
                    "mma.sync.aligned.m16n8k8.row.col.f32.tf32.tf32.f32 "
                    "{%0,%1,%2,%3}, {%4,%5,%6,%7}, {%8,%9}, {%0,%1,%2,%3};"
                    : "+f"(c[nt][0]), "+f"(c[nt][1]), "+f"(c[nt][2]), "+f"(c[nt][3])
                    : "r"(a[kk][0]), "r"(a[kk][1]), "r"(a[kk][2]), "r"(a[kk][3]),
                      "r"(b0), "r"(b1));
            }
        }

        // store to fp16 smem tile
        int ra = rg * 16 + g4, rb = ra + 8;
        #pragma unroll
        for (int nt = 0; nt < 8; nt++) {
            int col = p * GP + ch * 64 + nt * 8 + t4 * 2;
            *(__half2*)(hs + (size_t)ra * H_PITCH + col) = __floats2half2_rn(c[nt][0], c[nt][1]);
            *(__half2*)(hs + (size_t)rb * H_PITCH + col) = __floats2half2_rn(c[nt][2], c[nt][3]);
        }
    }
    __syncthreads();

    // ---- phase 2: edges for srcs [r0, r0+64) ----
    int estart = (r0 == 0) ? 0 : (G_CUR[r0 - 1] + g_bsum[(r0 - 1) >> 8]);
    int lastRow = min(r0 + GR - 1, N - 1);
    int eend = G_CUR[lastRow] + g_bsum[lastRow >> 8];

    int tot = eend - estart;
    if (tot <= 0) return;
    int per = (tot + 7) >> 3;
    int wb = estart + w * per;
    int we = min(wb + per, eend);
    if (wb >= we) return;

    __half2 hreg[12];
    float my_asrc = 0.0f;
    int cur_src = -1;

    int2 sd_next = g_srec[wb];
    float adst_n = 0.f, invd_n = 0.f;
    if (lane < 12) {
        adst_n = g_dst2[(size_t)sd_next.y * 24 + lane];
        invd_n = g_dst2[(size_t)sd_next.y * 24 + 12 + lane];
    }

    for (int e = wb; e < we; e++) {
        int2 sd = sd_next;
        float adst = adst_n, invd = invd_n;
        if (e + 1 < we) {
            sd_next = g_srec[e + 1];
            if (lane < 12) {
                adst_n = g_dst2[(size_t)sd_next.y * 24 + lane];
                invd_n = g_dst2[(size_t)sd_next.y * 24 + 12 + lane];
            }
        }
        int s = sd.x, d = sd.y;

        if (s != cur_src) {
            const __half2* hp = (const __half2*)(hs + (size_t)(s - r0) * H_PITCH);
            #pragma unroll
            for (int h = 0; h < 12; h++) hreg[h] = hp[h * 32 + lane];
            if (lane < 12) my_asrc = g_asrc[s * 12 + lane];
            cur_src = s;
        }

        float aw = 0.0f;
        if (lane < 12)
            aw = __expf(lrelu(my_asrc + adst)) * invd;

        float ax = 0.0f, ay = 0.0f;
        #pragma unroll
        for (int h = 0; h < 12; h++) {
            float wh = __shfl_sync(0xffffffffu, aw, h);
            float2 v = __half22float2(hreg[h]);
            ax = fmaf(wh, v.x, ax);
            ay = fmaf(wh, v.y, ay);
        }
        float* yp = G_Y + (size_t)d * 64 + lane * 2;
        asm volatile("red.global.add.v2.f32 [%0], {%1, %2};"
                     :: "l"(yp), "f"(ax), "f"(ay) : "memory");
    }
}

// ---- K7: out = relu(x + y + bias) ----
__global__ void k_final(const float* __restrict__ x,
                        const float* __restrict__ bias,
                        float* __restrict__ out, int N) {
    int i = blockIdx.x * blockDim.x + threadIdx.x;
    if (i >= N * 64) return;
    float v = x[i] + G_Y[i] + bias[i & 63];
    out[i] = v > 0.0f ? v : 0.0f;
}

extern "C" void kernel_launch(void* const* d_in, const int* in_sizes, int n_in,
                              void* d_out, int out_size) {
    const float* x       = (const float*)d_in[0];
    const int*   ei      = (const int*)  d_in[1];
    const float* W       = (const float*)d_in[2];
    const float* att_src = (const float*)d_in[3];
    const float* att_dst = (const float*)d_in[4];
    const float* bias    = (const float*)d_in[5];
    float* out = (float*)d_out;

    int N = in_sizes[0] / Cc;   // 50000
    int E = in_sizes[1] / 2;    // 400000
    int Et = E + N;
    int nScanBlocks = (N + 255) / 256;
    int nFusedBlocks = (N + GR - 1) / GR;

    cudaFuncSetAttribute(k_gemm_scatter,
                         cudaFuncAttributeMaxDynamicSharedMemorySize, FUSED_SMEM);

    // single memset node for all accumulators + done flag
    void* p_zbuf;
    cudaGetSymbolAddress(&p_zbuf, g_zbuf);
    cudaMemsetAsync(p_zbuf, 0, ZB_SIZE * 4, 0);

    k_wa<<<(Cc * 24 + 255) / 256, 256>>>(W, att_src, att_dst);
    k_attn<<<(N + 127) / 128, 512>>>(x, N);
    k_edge<<<(Et + 255) / 256, 256>>>(ei, E, N);
    k_scan1<<<nScanBlocks, 256>>>(N, nScanBlocks);
    k_perm<<<(Et + 255) / 256, 256>>>(ei, E, N);
    k_gemm_scatter<<<nFusedBlocks, 256, FUSED_SMEM>>>(x, W, N, Et);
    k_final<<<(N * Cc + 255) / 256, 256>>>(x, bias, out, N);
}

// round 16
// speedup vs baseline: 1.6934x; 1.6934x over previous
#include <cuda_runtime.h>
#include <cuda_fp16.h>
#include <cstdint>

#define NEG_SLOPE 0.2f
#define GAT_EPS 1e-16f

static constexpr int Nn  = 50000;
static constexpr int Cc  = 64;
static constexpr int Hh  = 12;
static constexpr int Ee  = 400000;
static constexpr int Etot_c = Ee + Nn;
static constexpr int NC  = Hh * Cc;   // 768
static constexpr int CHUNK = 16;      // sorted edges per warp in scatter

// GEMM tiling
static constexpr int GR = 128;
static constexpr int GP = 128;
static constexpr int XS_PITCH = 68;
static constexpr int WS_PITCH = 132;
static constexpr int GEMM_SMEM = (GR * XS_PITCH + Cc * WS_PITCH) * 4;

// ---- zeroed-every-launch blob: y | denom | cursor | done ----
static constexpr size_t ZB_DEN  = (size_t)Nn * Cc;
static constexpr size_t ZB_CUR  = ZB_DEN + (size_t)Nn * Hh;
static constexpr size_t ZB_DONE = ZB_CUR + Nn;
static constexpr size_t ZB_SIZE = ZB_DONE + 4;
__device__ float g_zbuf[ZB_SIZE];
#define G_Y    (g_zbuf)
#define G_DEN  (g_zbuf + ZB_DEN)
#define G_CUR  ((int*)(g_zbuf + ZB_CUR))
#define G_DONE ((int*)(g_zbuf + ZB_DONE))

// ---- other scratch ----
__device__ __half   g_h[(size_t)Nn * NC];     // 76.8 MB projected features (fp16)
__device__ float    g_asrc[Nn * Hh];
__device__ float    g_dst2[Nn * 24];          // [0..11]=a_dst, [12..23]=inv denom/12
__device__ float    g_wa[Cc * 24];
__device__ int      g_bsum[256];
__device__ int2     g_srec[Etot_c];

// Side stream + events, created at static-init time (proven safe in R8).
struct SideStream {
    cudaStream_t s2 = nullptr;
    cudaEvent_t evFork = nullptr, evJoin = nullptr;
    bool ok = false;
    SideStream() {
        ok = (cudaStreamCreateWithFlags(&s2, cudaStreamNonBlocking) == cudaSuccess)
          && (cudaEventCreateWithFlags(&evFork, cudaEventDisableTiming) == cudaSuccess)
          && (cudaEventCreateWithFlags(&evJoin, cudaEventDisableTiming) == cudaSuccess);
    }
};
static SideStream g_ss;

__device__ __forceinline__ float lrelu(float v) {
    return v > 0.0f ? v : NEG_SLOPE * v;
}
__device__ __forceinline__ float to_tf32(float v) {
    uint32_t b;
    asm("cvt.rna.tf32.f32 %0, %1;" : "=r"(b) : "f"(v));
    return __uint_as_float(b);
}

// ---- K1: fold attention vectors through W ----
__global__ void k_wa(const float* __restrict__ W,
                     const float* __restrict__ att_src,
                     const float* __restrict__ att_dst) {
    int t = blockIdx.x * blockDim.x + threadIdx.x;
    if (t >= Cc * 24) return;
    int k = t / 24, j = t % 24;
    int h = j >> 1;
    const float* att = (j & 1) ? att_dst : att_src;
    float s = 0.0f;
    #pragma unroll 8
    for (int c = 0; c < Cc; c++) s += W[k * NC + h * Cc + c] * att[h * Cc + c];
    g_wa[k * 24 + j] = s;
}

// ---- K2: h = x @ W via tf32 mma.sync; fp16 store (adjacent-col pairs) ----
__global__ void __launch_bounds__(256) k_gemm(const float* __restrict__ x,
                                              const float* __restrict__ W,
                                              int N) {
    extern __shared__ float sm[];
    float* xs = sm;
    float* ws = sm + GR * XS_PITCH;

    int t = threadIdx.x;
    int lane = t & 31, w = t >> 5;
    int g4 = lane >> 2, t4 = lane & 3;
    int r0 = blockIdx.x * GR;

    {
        const float4* x4 = (const float4*)(x + (size_t)r0 * Cc);
        #pragma unroll
        for (int j = 0; j < 8; j++) {
            int idx = t + j * 256;
            int row = idx >> 4, c4 = (idx & 15) << 2;
            float4 v = make_float4(0.f, 0.f, 0.f, 0.f);
            if (r0 + row < N) v = x4[idx];
            float* p = xs + row * XS_PITCH + c4;
            p[0] = to_tf32(v.x); p[1] = to_tf32(v.y);
            p[2] = to_tf32(v.z); p[3] = to_tf32(v.w);
        }
    }
    __syncthreads();

    uint32_t a[8][4];
    #pragma unroll
    for (int kk = 0; kk < 8; kk++) {
        int c0 = kk * 8 + t4;
        a[kk][0] = __float_as_uint(xs[(w * 16 + g4)     * XS_PITCH + c0]);
        a[kk][1] = __float_as_uint(xs[(w * 16 + g4 + 8) * XS_PITCH + c0]);
        a[kk][2] = __float_as_uint(xs[(w * 16 + g4)     * XS_PITCH + c0 + 4]);
        a[kk][3] = __float_as_uint(xs[(w * 16 + g4 + 8) * XS_PITCH + c0 + 4]);
    }

    for (int p = 0; p < NC / GP; p++) {
        __syncthreads();
        {
            const float4* W4 = (const float4*)W;
            int n0f4 = p * (GP / 4);
            #pragma unroll
            for (int j = 0; j < 8; j++) {
                int idx = t + j * 256;
                int k = idx >> 5, n4 = (idx & 31) << 2;
                float4 v = W4[(size_t)k * (NC / 4) + n0f4 + (n4 >> 2)];
                float* q = ws + k * WS_PITCH + n4;
                q[0] = to_tf32(v.x); q[1] = to_tf32(v.y);
                q[2] = to_tf32(v.z); q[3] = to_tf32(v.w);
            }
        }
        __syncthreads();

        float c[16][4];
        #pragma unroll
        for (int nt = 0; nt < 16; nt++)
            #pragma unroll
            for (int q = 0; q < 4; q++) c[nt][q] = 0.0f;

        #pragma unroll
        for (int kk = 0; kk < 8; kk++) {
            const float* wrow0 = ws + (kk * 8 + t4) * WS_PITCH;
            const float* wrow1 = wrow0 + 4 * WS_PITCH;
            #pragma unroll
            for (int nt = 0; nt < 16; nt++) {
                uint32_t b0 = __float_as_uint(wrow0[nt * 8 + g4]);
                uint32_t b1 = __float_as_uint(wrow1[nt * 8 + g4]);
                asm volatile(
                    "mma.sync.aligned.m16n8k8.row.col.f32.tf32.tf32.f32 "
                    "{%0,%1,%2,%3}, {%4,%5,%6,%7}, {%8,%9}, {%0,%1,%2,%3};"
                    : "+f"(c[nt][0]), "+f"(c[nt][1]), "+f"(c[nt][2]), "+f"(c[nt][3])
                    : "r"(a[kk][0]), "r"(a[kk][1]), "r"(a[kk][2]), "r"(a[kk][3]),
                      "r"(b0), "r"(b1));
            }
        }

        // fp16 store: each thread owns adjacent column pair -> direct half2
        int rowa = r0 + w * 16 + g4;
        int rowb = rowa + 8;
        #pragma unroll
        for (int nt = 0; nt < 16; nt++) {
            int col = p * GP + nt * 8 + t4 * 2;
            if (rowa < N)
                *(__half2*)(g_h + (size_t)rowa * NC + col) = __floats2half2_rn(c[nt][0], c[nt][1]);
            if (rowb < N)
                *(__half2*)(g_h + (size_t)rowb * NC + col) = __floats2half2_rn(c[nt][2], c[nt][3]);
        }
    }
}

// ---- K3: a_src/a_dst = x @ Wa  (128 rows, 512 threads) ----
__global__ void __launch_bounds__(512) k_attn(const float* __restrict__ x, int N) {
    __shared__ float xsh[128 * 65];
    __shared__ float was[64 * 24];
    int t = threadIdx.x;
    for (int i = t; i < 64 * 24; i += 512) was[i] = g_wa[i];
    int r0 = blockIdx.x * 128;
    for (int i = t; i < 2048; i += 512) {
        int rr = i >> 4, kk = (i & 15) << 2;
        float4 v = make_float4(0.f, 0.f, 0.f, 0.f);
        if (r0 + rr < N) v = ((const float4*)(x + (size_t)r0 * 64))[i];
        xsh[rr * 65 + kk + 0] = v.x;
        xsh[rr * 65 + kk + 1] = v.y;
        xsh[rr * 65 + kk + 2] = v.z;
        xsh[rr * 65 + kk + 3] = v.w;
    }
    __syncthreads();
    int r = t >> 2, q = t & 3;
    int n = r0 + r;
    float acc[6] = {0.f, 0.f, 0.f, 0.f, 0.f, 0.f};
    #pragma unroll 8
    for (int k = 0; k < 64; k++) {
        float xv = xsh[r * 65 + k];
        #pragma unroll
        for (int j = 0; j < 6; j++) acc[j] += xv * was[k * 24 + q * 6 + j];
    }
    if (n < N) {
        #pragma unroll
        for (int j = 0; j < 6; j++) {
            int jj = q * 6 + j, h = jj >> 1;
            if (jj & 1) g_dst2[n * 24 + h] = acc[j];
            else        g_asrc[n * 12 + h] = acc[j];
        }
    }
}

// ---- K4: fused edge pass: src-histogram + denom via vectorized REDs ----
__global__ void k_edge(const int* __restrict__ ei, int E, int N) {
    int e = blockIdx.x * blockDim.x + threadIdx.x;
    int Et = E + N;
    if (e >= Et) return;
    int s, d;
    if (e < E) { s = ei[e]; d = ei[E + e]; } else { s = d = e - E; }
    atomicAdd(&G_CUR[s], 1);
    const float4* As = (const float4*)(g_asrc + (size_t)s * 12);
    const float4* Ad = (const float4*)(g_dst2 + (size_t)d * 24);
    float* den = G_DEN + (size_t)d * 12;
    #pragma unroll
    for (int i = 0; i < 3; i++) {
        float4 a = As[i], b = Ad[i];
        float e0 = __expf(lrelu(a.x + b.x));
        float e1 = __expf(lrelu(a.y + b.y));
        float e2 = __expf(lrelu(a.z + b.z));
        float e3 = __expf(lrelu(a.w + b.w));
        asm volatile("red.global.add.v4.f32 [%0], {%1, %2, %3, %4};"
                     :: "l"(den + i * 4), "f"(e0), "f"(e1), "f"(e2), "f"(e3)
                     : "memory");
    }
}

// ---- K5: fused: invd + cursor scan + (last block) bsum scan ----
__global__ void k_scan1(int N, int nb) {
    __shared__ int wsum[8];
    __shared__ int isLast;
    int b = blockIdx.x, t = threadIdx.x, i = b * 256 + t;
    int lane = t & 31, w = t >> 5;

    if (i < N) {
        const float4* dn = (const float4*)(G_DEN + (size_t)i * 12);
        float4* q = (float4*)(g_dst2 + (size_t)i * 24 + 12);
        #pragma unroll
        for (int k = 0; k < 3; k++) {
            float4 v = dn[k], o;
            o.x = 1.0f / (v.x + GAT_EPS) * (1.0f / 12.0f);
            o.y = 1.0f / (v.y + GAT_EPS) * (1.0f / 12.0f);
            o.z = 1.0f / (v.z + GAT_EPS) * (1.0f / 12.0f);
            o.w = 1.0f / (v.w + GAT_EPS) * (1.0f / 12.0f);
            q[k] = o;
        }
    }

    int v = (i < N) ? G_CUR[i] : 0;
    int incl = v;
    #pragma unroll
    for (int o = 1; o < 32; o <<= 1) {
        int nv = __shfl_up_sync(~0u, incl, o);
        if (lane >= o) incl += nv;
    }
    if (lane == 31) wsum[w] = incl;
    __syncthreads();
    if (w == 0) {
        int s = (lane < 8) ? wsum[lane] : 0;
        #pragma unroll
        for (int o = 1; o < 8; o <<= 1) {
            int nv = __shfl_up_sync(~0u, s, o);
            if (lane >= o) s += nv;
        }
        if (lane < 8) wsum[lane] = s;
    }
    __syncthreads();
    int excl = (w > 0 ? wsum[w - 1] : 0) + incl - v;
    if (i < N) G_CUR[i] = excl;
    if (t == 255) g_bsum[b] = wsum[7];

    __threadfence();
    if (t == 0) {
        int prev = atomicAdd(G_DONE, 1);
        isLast = (prev == nb - 1) ? 1 : 0;
    }
    __syncthreads();
    if (isLast) {
        int val = (t < nb) ? g_bsum[t] : 0;
        int inc2 = val;
        #pragma unroll
        for (int o = 1; o < 32; o <<= 1) {
            int nv = __shfl_up_sync(~0u, inc2, o);
            if (lane >= o) inc2 += nv;
        }
        __syncthreads();
        if (lane == 31) wsum[w] = inc2;
        __syncthreads();
        if (w == 0) {
            int s = (lane < 8) ? wsum[lane] : 0;
            #pragma unroll
            for (int o = 1; o < 8; o <<= 1) {
                int nv = __shfl_up_sync(~0u, s, o);
                if (lane >= o) s += nv;
            }
            if (lane < 8) wsum[lane] = s;
        }
        __syncthreads();
        int ex2 = (w > 0 ? wsum[w - 1] : 0) + inc2 - val;
        if (t < nb) g_bsum[t] = ex2;
    }
}

// ---- K6: permute with fused block-offset add ----
__global__ void k_perm(const int* __restrict__ ei, int E, int N) {
    int e = blockIdx.x * blockDim.x + threadIdx.x;
    int Et = E + N;
    if (e >= Et) return;
    int s, d;
    if (e < E) { s = ei[e]; d = ei[E + e]; } else { s = d = e - E; }
    int pos = atomicAdd(&G_CUR[s], 1) + g_bsum[s >> 8];
    g_srec[pos] = make_int2(s, d);
}

// ---- K7: scatter over src-sorted pairs; fp16 h gathers, fp32 math ----
__global__ void __launch_bounds__(256) k_scatter2(int E, int N) {
    int warp = (blockIdx.x * blockDim.x + threadIdx.x) >> 5;
    int lane = threadIdx.x & 31;
    int Et = E + N;
    int base = warp * CHUNK;
    if (base >= Et) return;

    __half2 hreg[12];
    float my_asrc = 0.0f;
    int cur_src = -1;
    int lim = min(CHUNK, Et - base);

    int2 sd_next = g_srec[base];
    for (int j = 0; j < lim; j++) {
        int2 sd = sd_next;
        if (j + 1 < lim) sd_next = g_srec[base + j + 1];
        int s = sd.x, d = sd.y;

        if (s != cur_src) {
            const __half2* hp = (const __half2*)(g_h + (size_t)s * NC);
            #pragma unroll
            for (int h = 0; h < 12; h++) hreg[h] = hp[h * 32 + lane];
            if (lane < 12) my_asrc = g_asrc[s * 12 + lane];
            cur_src = s;
        }

        float aw = 0.0f;
        if (lane < 12) {
            float adst = g_dst2[d * 24 + lane];
            float invd = g_dst2[d * 24 + 12 + lane];
            aw = __expf(lrelu(my_asrc + adst)) * invd;
        }

        float ax = 0.0f, ay = 0.0f;
        #pragma unroll
        for (int h = 0; h < 12; h++) {
            float wh = __shfl_sync(0xffffffffu, aw, h);
            float2 v = __half22float2(hreg[h]);
            ax = fmaf(wh, v.x, ax);
            ay = fmaf(wh, v.y, ay);
        }
        float* yp = G_Y + (size_t)d * 64 + lane * 2;
        asm volatile("red.global.add.v2.f32 [%0], {%1, %2};"
                     :: "l"(yp), "f"(ax), "f"(ay) : "memory");
    }
}

// ---- K8: out = relu(x + y + bias) ----
__global__ void k_final(const float* __restrict__ x,
                        const float* __restrict__ bias,
                        float* __restrict__ out, int N) {
    int i = blockIdx.x * blockDim.x + threadIdx.x;
    if (i >= N * 64) return;
    float v = x[i] + G_Y[i] + bias[i & 63];
    out[i] = v > 0.0f ? v : 0.0f;
}

extern "C" void kernel_launch(void* const* d_in, const int* in_sizes, int n_in,
                              void* d_out, int out_size) {
    const float* x       = (const float*)d_in[0];
    const int*   ei      = (const int*)  d_in[1];
    const float* W       = (const float*)d_in[2];
    const float* att_src = (const float*)d_in[3];
    const float* att_dst = (const float*)d_in[4];
    const float* bias    = (const float*)d_in[5];
    float* out = (float*)d_out;

    int N = in_sizes[0] / Cc;   // 50000
    int E = in_sizes[1] / 2;    // 400000
    int Et = E + N;
    int nScanBlocks = (N + 255) / 256;
    int nGemmBlocks = (N + GR - 1) / GR;

    cudaFuncSetAttribute(k_gemm, cudaFuncAttributeMaxDynamicSharedMemorySize,
                         GEMM_SMEM);

    // single memset node for all accumulators + done flag
    void* p_zbuf;
    cudaGetSymbolAddress(&p_zbuf, g_zbuf);
    cudaMemsetAsync(p_zbuf, 0, ZB_SIZE * 4, 0);

    bool fork = g_ss.ok;
    if (fork) {
        cudaEventRecord(g_ss.evFork, 0);
        cudaStreamWaitEvent(g_ss.s2, g_ss.evFork, 0);
        k_gemm<<<nGemmBlocks, 256, GEMM_SMEM, g_ss.s2>>>(x, W, N);
        cudaEventRecord(g_ss.evJoin, g_ss.s2);
    }

    k_wa<<<(Cc * 24 + 255) / 256, 256>>>(W, att_src, att_dst);
    k_attn<<<(N + 127) / 128, 512>>>(x, N);
    k_edge<<<(Et + 255) / 256, 256>>>(ei, E, N);
    k_scan1<<<nScanBlocks, 256>>>(N, nScanBlocks);
    k_perm<<<(Et + 255) / 256, 256>>>(ei, E, N);

    if (fork) {
        cudaStreamWaitEvent(0, g_ss.evJoin, 0);
    } else {
        k_gemm<<<nGemmBlocks, 256, GEMM_SMEM>>>(x, W, N);
    }
    {
        int nWarps = (Et + CHUNK - 1) / CHUNK;
        int nBlocks = (nWarps * 32 + 255) / 256;
        k_scatter2<<<nBlocks, 256>>>(E, N);
    }
    k_final<<<(N * Cc + 255) / 256, 256>>>(x, bias, out, N);
}